// round 10
// baseline (speedup 1.0000x reference)
#include <cuda_runtime.h>
#include <cuda_fp16.h>
#include <string.h>

#define NM 128
#define NM3 (NM * NM * NM)
#define NC 16
#define NPTS 100000
#define INV_SPACING 10.0f

// Scratch: mesh transposed to (x,y,z,c) fp16 layout.
// One cell = 16 halfs = 32 bytes = one ulonglong4 (accessed as LDG/STG.256).
__device__ ulonglong4 g_scratch[NM3];

static __device__ __forceinline__ unsigned h2u(__half2 h) {
    unsigned u; memcpy(&u, &h, 4); return u;
}
static __device__ __forceinline__ __half2 u2h(unsigned u) {
    __half2 h; memcpy(&h, &u, 4); return h;
}
static __device__ __forceinline__ unsigned long long pack64(unsigned lo, unsigned hi) {
    return (unsigned long long)lo | ((unsigned long long)hi << 32);
}

// --- 256-bit L2-pinned scratch access (evict_last requires .v4.b64) ---------
static __device__ __forceinline__ void st_cell_evict_last(ulonglong4* p, ulonglong4 v) {
    asm volatile("st.global.L2::evict_last.v4.b64 [%0], {%1,%2,%3,%4};"
                 :: "l"(p), "l"(v.x), "l"(v.y), "l"(v.z), "l"(v.w) : "memory");
}
static __device__ __forceinline__ ulonglong4 ld_cell_evict_last(const ulonglong4* p) {
    ulonglong4 r;
    asm("ld.global.nc.L2::evict_last.v4.b64 {%0,%1,%2,%3}, [%4];"
        : "=l"(r.x), "=l"(r.y), "=l"(r.z), "=l"(r.w) : "l"(p));
    return r;
}

// ---------------------------------------------------------------------------
// Kernel 1: transpose (c, cell)f32 -> (cell, c)f16   [at DRAM roofline]
// ---------------------------------------------------------------------------
__global__ void mesh_transpose_f16_kernel(const float* __restrict__ in) {
    int q = blockIdx.x * blockDim.x + threadIdx.x;   // quad-cell index
    if (q >= NM3 / 4) return;
    int cell0 = q * 4;

    float4 v[NC];
#pragma unroll
    for (int c = 0; c < NC; c++) {
        v[c] = __ldcs((const float4*)(in + (size_t)c * NM3 + cell0));
    }

#pragma unroll
    for (int z = 0; z < 4; z++) {
        float f[NC];
#pragma unroll
        for (int c = 0; c < NC; c++) {
            f[c] = (z == 0) ? v[c].x : (z == 1) ? v[c].y : (z == 2) ? v[c].z : v[c].w;
        }
        ulonglong4 cell;
        cell.x = pack64(h2u(__floats2half2_rn(f[0],  f[1])),
                        h2u(__floats2half2_rn(f[2],  f[3])));
        cell.y = pack64(h2u(__floats2half2_rn(f[4],  f[5])),
                        h2u(__floats2half2_rn(f[6],  f[7])));
        cell.z = pack64(h2u(__floats2half2_rn(f[8],  f[9])),
                        h2u(__floats2half2_rn(f[10], f[11])));
        cell.w = pack64(h2u(__floats2half2_rn(f[12], f[13])),
                        h2u(__floats2half2_rn(f[14], f[15])));
        st_cell_evict_last(&g_scratch[cell0 + z], cell);
    }
}

// ---------------------------------------------------------------------------
// Kernel 2: TSC interpolation.
// 2 threads per point (adjacent lanes). Taps split by parity of the linear
// tap index (14/13). Each tap = one 32B LDG.256 of the whole cell (16 ch).
// Partial sums combined with 16 shfl_xor adds; even lane stores 64B.
// ---------------------------------------------------------------------------
__global__ void interp_f16_kernel(const float* __restrict__ points,
                                  float4* __restrict__ out) {
    int t = blockIdx.x * blockDim.x + threadIdx.x;
    int p = t >> 1;
    int s = t & 1;                 // tap-parity this thread owns
    bool valid = (p < NPTS);
    if (p >= NPTS) p = NPTS - 1;   // clamp: keep whole warp active for shfl

    float px = points[p * 3 + 0] * INV_SPACING;
    float py = points[p * 3 + 1] * INV_SPACING;
    float pz = points[p * 3 + 2] * INV_SPACING;

    float rx = rintf(px), ry = rintf(py), rz = rintf(pz);
    float dx = px - rx, dy = py - ry, dz = pz - rz;
    int ix = (int)rx, iy = (int)ry, iz = (int)rz;

    float wx[3], wy[3], wz[3];
    {
        float a;
        a = 2.0f * dx - 1.0f; wx[0] = a * a * 0.125f;
        wx[1] = 0.75f - dx * dx;
        a = 2.0f * dx + 1.0f; wx[2] = a * a * 0.125f;

        a = 2.0f * dy - 1.0f; wy[0] = a * a * 0.125f;
        wy[1] = 0.75f - dy * dy;
        a = 2.0f * dy + 1.0f; wy[2] = a * a * 0.125f;

        a = 2.0f * dz - 1.0f; wz[0] = a * a * 0.125f;
        wz[1] = 0.75f - dz * dz;
        a = 2.0f * dz + 1.0f; wz[2] = a * a * 0.125f;
    }

    int xs[3], ys[3], zs[3];
    xs[0] = (ix + 127) & (NM - 1); xs[1] = ix & (NM - 1); xs[2] = (ix + 129) & (NM - 1);
    ys[0] = (iy + 127) & (NM - 1); ys[1] = iy & (NM - 1); ys[2] = (iy + 129) & (NM - 1);
    zs[0] = (iz + 127) & (NM - 1); zs[1] = iz & (NM - 1); zs[2] = (iz + 129) & (NM - 1);

    float acc[NC];
#pragma unroll
    for (int c = 0; c < NC; c++) acc[c] = 0.0f;

#pragma unroll
    for (int ox = 0; ox < 3; ox++) {
#pragma unroll
        for (int oy = 0; oy < 3; oy++) {
            float wxy = wx[ox] * wy[oy];
            int rowbase = (xs[ox] * NM + ys[oy]) * NM;
#pragma unroll
            for (int oz = 0; oz < 3; oz++) {
                int tap = ox * 9 + oy * 3 + oz;
                if ((tap & 1) != s) continue;   // compile-time split (unrolled)
                float w = wxy * wz[oz];
                ulonglong4 raw = ld_cell_evict_last(&g_scratch[rowbase + zs[oz]]);
                unsigned long long qd[4] = {raw.x, raw.y, raw.z, raw.w};
#pragma unroll
                for (int j = 0; j < 4; j++) {
                    float2 f0 = __half22float2(u2h((unsigned)qd[j]));
                    float2 f1 = __half22float2(u2h((unsigned)(qd[j] >> 32)));
                    acc[j * 4 + 0] += w * f0.x;
                    acc[j * 4 + 1] += w * f0.y;
                    acc[j * 4 + 2] += w * f1.x;
                    acc[j * 4 + 3] += w * f1.y;
                }
            }
        }
    }

    // Pairwise reduce across the two lanes owning this point.
#pragma unroll
    for (int c = 0; c < NC; c++) {
        acc[c] += __shfl_xor_sync(0xffffffffu, acc[c], 1);
    }

    if (valid && s == 0) {
        float4* o = out + (size_t)p * 4;
        __stcs(o + 0, make_float4(acc[0],  acc[1],  acc[2],  acc[3]));
        __stcs(o + 1, make_float4(acc[4],  acc[5],  acc[6],  acc[7]));
        __stcs(o + 2, make_float4(acc[8],  acc[9],  acc[10], acc[11]));
        __stcs(o + 3, make_float4(acc[12], acc[13], acc[14], acc[15]));
    }
}

extern "C" void kernel_launch(void* const* d_in, const int* in_sizes, int n_in,
                              void* d_out, int out_size) {
    const float* mesh = (const float*)d_in[0];    // (16, 128, 128, 128) f32
    const float* points = (const float*)d_in[1];  // (100000, 3) f32
    float4* out = (float4*)d_out;                 // (100000, 16) f32

    {
        int threads = 256;
        int blocks = (NM3 / 4 + threads - 1) / threads;
        mesh_transpose_f16_kernel<<<blocks, threads>>>(mesh);
    }
    {
        int total = NPTS * 2;
        int threads = 256;
        int blocks = (total + threads - 1) / threads;
        interp_f16_kernel<<<blocks, threads>>>(points, out);
    }
}

// round 11
// speedup vs baseline: 1.0916x; 1.0916x over previous
#include <cuda_runtime.h>
#include <cuda_fp16.h>
#include <string.h>

#define NM 128
#define NM3 (NM * NM * NM)
#define NC 16
#define NPTS 100000
#define INV_SPACING 10.0f

// Scratch: mesh transposed to (x,y,z,c) fp16 layout.
// One cell = 16 halfs = 32 bytes = one ulonglong4 (accessed as LDG/STG.256).
__device__ ulonglong4 g_scratch[NM3];

static __device__ __forceinline__ unsigned h2u(__half2 h) {
    unsigned u; memcpy(&u, &h, 4); return u;
}
static __device__ __forceinline__ __half2 u2h(unsigned u) {
    __half2 h; memcpy(&h, &u, 4); return h;
}
static __device__ __forceinline__ unsigned long long pack64(unsigned lo, unsigned hi) {
    return (unsigned long long)lo | ((unsigned long long)hi << 32);
}

// --- 256-bit L2-pinned scratch access (evict_last requires .v4.b64) ---------
static __device__ __forceinline__ void st_cell_evict_last(ulonglong4* p, ulonglong4 v) {
    asm volatile("st.global.L2::evict_last.v4.b64 [%0], {%1,%2,%3,%4};"
                 :: "l"(p), "l"(v.x), "l"(v.y), "l"(v.z), "l"(v.w) : "memory");
}
static __device__ __forceinline__ ulonglong4 ld_cell_evict_last(const ulonglong4* p) {
    ulonglong4 r;
    asm("ld.global.nc.L2::evict_last.v4.b64 {%0,%1,%2,%3}, [%4];"
        : "=l"(r.x), "=l"(r.y), "=l"(r.z), "=l"(r.w) : "l"(p));
    return r;
}

// ---------------------------------------------------------------------------
// Kernel 1: transpose (c, cell)f32 -> (cell, c)f16   [at DRAM roofline]
// ---------------------------------------------------------------------------
__global__ void mesh_transpose_f16_kernel(const float* __restrict__ in) {
    int q = blockIdx.x * blockDim.x + threadIdx.x;   // quad-cell index
    if (q >= NM3 / 4) return;
    int cell0 = q * 4;

    float4 v[NC];
#pragma unroll
    for (int c = 0; c < NC; c++) {
        v[c] = __ldcs((const float4*)(in + (size_t)c * NM3 + cell0));
    }

#pragma unroll
    for (int z = 0; z < 4; z++) {
        float f[NC];
#pragma unroll
        for (int c = 0; c < NC; c++) {
            f[c] = (z == 0) ? v[c].x : (z == 1) ? v[c].y : (z == 2) ? v[c].z : v[c].w;
        }
        ulonglong4 cell;
        cell.x = pack64(h2u(__floats2half2_rn(f[0],  f[1])),
                        h2u(__floats2half2_rn(f[2],  f[3])));
        cell.y = pack64(h2u(__floats2half2_rn(f[4],  f[5])),
                        h2u(__floats2half2_rn(f[6],  f[7])));
        cell.z = pack64(h2u(__floats2half2_rn(f[8],  f[9])),
                        h2u(__floats2half2_rn(f[10], f[11])));
        cell.w = pack64(h2u(__floats2half2_rn(f[12], f[13])),
                        h2u(__floats2half2_rn(f[14], f[15])));
        st_cell_evict_last(&g_scratch[cell0 + z], cell);
    }
}

// ---------------------------------------------------------------------------
// Kernel 2: TSC interpolation, warp-paired tap split.
// Warps 2i and 2i+1 cover the SAME 32 points; warp parity s picks even (14)
// or odd (13) taps. s is warp-uniform -> every tap load is a full-width 32B
// LDG.256 (all 16 channels of one cell), no lane predication waste.
// Odd warp dumps fp32 partials to padded smem; even warp adds + stores 64B.
// ---------------------------------------------------------------------------
__global__ void interp_f16_kernel(const float* __restrict__ points,
                                  float4* __restrict__ out) {
    __shared__ float part[4][32][NC + 1];   // +1 pad: conflict-free smem

    int warp = threadIdx.x >> 5;
    int lane = threadIdx.x & 31;
    int pair = warp >> 1;       // 0..3
    int s = warp & 1;           // tap parity owned by this warp (uniform)
    int p = blockIdx.x * 128 + pair * 32 + lane;
    bool valid = (p < NPTS);
    int pc = valid ? p : (NPTS - 1);   // clamp: no early return (barrier below)

    float px = points[pc * 3 + 0] * INV_SPACING;
    float py = points[pc * 3 + 1] * INV_SPACING;
    float pz = points[pc * 3 + 2] * INV_SPACING;

    float rx = rintf(px), ry = rintf(py), rz = rintf(pz);
    float dx = px - rx, dy = py - ry, dz = pz - rz;
    int ix = (int)rx, iy = (int)ry, iz = (int)rz;

    float wx[3], wy[3], wz[3];
    {
        float a;
        a = 2.0f * dx - 1.0f; wx[0] = a * a * 0.125f;
        wx[1] = 0.75f - dx * dx;
        a = 2.0f * dx + 1.0f; wx[2] = a * a * 0.125f;

        a = 2.0f * dy - 1.0f; wy[0] = a * a * 0.125f;
        wy[1] = 0.75f - dy * dy;
        a = 2.0f * dy + 1.0f; wy[2] = a * a * 0.125f;

        a = 2.0f * dz - 1.0f; wz[0] = a * a * 0.125f;
        wz[1] = 0.75f - dz * dz;
        a = 2.0f * dz + 1.0f; wz[2] = a * a * 0.125f;
    }

    int xs[3], ys[3], zs[3];
    xs[0] = (ix + 127) & (NM - 1); xs[1] = ix & (NM - 1); xs[2] = (ix + 129) & (NM - 1);
    ys[0] = (iy + 127) & (NM - 1); ys[1] = iy & (NM - 1); ys[2] = (iy + 129) & (NM - 1);
    zs[0] = (iz + 127) & (NM - 1); zs[1] = iz & (NM - 1); zs[2] = (iz + 129) & (NM - 1);

    float acc[NC];
#pragma unroll
    for (int c = 0; c < NC; c++) acc[c] = 0.0f;

    // One tap: full-cell 32B load + 16 fp32 FMAs.
    auto do_tap = [&](int ox, int oy, int oz) {
        float w = wx[ox] * wy[oy] * wz[oz];
        int cellidx = (xs[ox] * NM + ys[oy]) * NM + zs[oz];
        ulonglong4 raw = ld_cell_evict_last(&g_scratch[cellidx]);
        unsigned long long qd[4] = {raw.x, raw.y, raw.z, raw.w};
#pragma unroll
        for (int j = 0; j < 4; j++) {
            float2 f0 = __half22float2(u2h((unsigned)qd[j]));
            float2 f1 = __half22float2(u2h((unsigned)(qd[j] >> 32)));
            acc[j * 4 + 0] += w * f0.x;
            acc[j * 4 + 1] += w * f0.y;
            acc[j * 4 + 2] += w * f1.x;
            acc[j * 4 + 3] += w * f1.y;
        }
    };

    if (s == 0) {   // uniform branch: even taps (14), fully unrolled
#pragma unroll
        for (int ox = 0; ox < 3; ox++)
#pragma unroll
            for (int oy = 0; oy < 3; oy++)
#pragma unroll
                for (int oz = 0; oz < 3; oz++)
                    if (((ox * 9 + oy * 3 + oz) & 1) == 0) do_tap(ox, oy, oz);
    } else {        // odd taps (13)
#pragma unroll
        for (int ox = 0; ox < 3; ox++)
#pragma unroll
            for (int oy = 0; oy < 3; oy++)
#pragma unroll
                for (int oz = 0; oz < 3; oz++)
                    if (((ox * 9 + oy * 3 + oz) & 1) == 1) do_tap(ox, oy, oz);
    }

    if (s == 1) {
#pragma unroll
        for (int c = 0; c < NC; c++) part[pair][lane][c] = acc[c];
    }
    __syncthreads();

    if (s == 0 && valid) {
#pragma unroll
        for (int c = 0; c < NC; c++) acc[c] += part[pair][lane][c];
        float4* o = out + (size_t)p * 4;
        __stcs(o + 0, make_float4(acc[0],  acc[1],  acc[2],  acc[3]));
        __stcs(o + 1, make_float4(acc[4],  acc[5],  acc[6],  acc[7]));
        __stcs(o + 2, make_float4(acc[8],  acc[9],  acc[10], acc[11]));
        __stcs(o + 3, make_float4(acc[12], acc[13], acc[14], acc[15]));
    }
}

extern "C" void kernel_launch(void* const* d_in, const int* in_sizes, int n_in,
                              void* d_out, int out_size) {
    const float* mesh = (const float*)d_in[0];    // (16, 128, 128, 128) f32
    const float* points = (const float*)d_in[1];  // (100000, 3) f32
    float4* out = (float4*)d_out;                 // (100000, 16) f32

    {
        int threads = 256;
        int blocks = (NM3 / 4 + threads - 1) / threads;
        mesh_transpose_f16_kernel<<<blocks, threads>>>(mesh);
    }
    {
        // 128 points per block (4 warp-pairs x 32 points), 2 warps per 32 pts
        int blocks = (NPTS + 127) / 128;
        interp_f16_kernel<<<blocks, 256>>>(points, out);
    }
}